// round 10
// baseline (speedup 1.0000x reference)
#include <cuda_runtime.h>
#include <cuda_bf16.h>
#include <cstdint>

#define N_NODES 50000
#define N_EDGES 625000
#define F 128
#define SCAN_BLOCKS 49          // 49 * 1024 = 50176 >= N_NODES
#define TILE_M 128
#define GEMM_BLOCKS ((N_NODES + TILE_M - 1) / TILE_M)   // 391
#define GEMM_THREADS 512
#define SPAD 136                // padded row stride (bf16 elems) -> conflict-free LDSM
#define TILE_BYTES (128 * SPAD * 2)
#define GEMM_SMEM (4 * TILE_BYTES)                      // Ah, Al, Bh, Bl = 139264 B
#define AGG_FLAG (1 << 30)

// ---------------------------------------------------------------------------
// Scratch (__device__ globals => allocation-free)
// Invariant: g_count[] == 0 at entry of every kernel_launch call.
//   - zero-initialized at module load (first call)
//   - the fused scatter's atomicSub cursor returns every element to 0 each call
// ---------------------------------------------------------------------------
__device__ float g_support[(size_t)N_NODES * F];   // x @ W (25.6 MB)
__device__ int   g_count[N_NODES];                 // histogram / cursor
__device__ int   g_start[N_NODES + 1];             // CSR row starts
__device__ int2  g_edge[N_EDGES];                  // packed {col, val} by row
__device__ int   g_agg[SCAN_BLOCKS];               // lookback aggregates

__device__ __forceinline__ uint32_t smem_u32(const void* p) {
    uint32_t a;
    asm("{ .reg .u64 t; cvta.to.shared.u64 t, %1; cvt.u32.u64 %0, t; }" : "=r"(a) : "l"(p));
    return a;
}

#define LDSM4(r0, r1, r2, r3, addr)                                              \
    asm volatile("ldmatrix.sync.aligned.m8n8.x4.shared.b16 {%0,%1,%2,%3}, [%4];" \
                 : "=r"(r0), "=r"(r1), "=r"(r2), "=r"(r3) : "r"(addr))

#define MMA16816(c, a0, a1, a2, a3, b0, b1)                                      \
    asm volatile("mma.sync.aligned.m16n8k16.row.col.f32.bf16.bf16.f32 "          \
                 "{%0,%1,%2,%3}, {%4,%5,%6,%7}, {%8,%9}, {%0,%1,%2,%3};"         \
                 : "+f"((c)[0]), "+f"((c)[1]), "+f"((c)[2]), "+f"((c)[3])        \
                 : "r"(a0), "r"(a1), "r"(a2), "r"(a3), "r"(b0), "r"(b1))

// ---------------------------------------------------------------------------
// Kernel 1: histogram of edge rows + lookback-flag reset
// ---------------------------------------------------------------------------
__global__ void hist_kernel(const int* __restrict__ rows) {
    const int gid = blockIdx.x * blockDim.x + threadIdx.x;
    if (gid < N_EDGES) atomicAdd(&g_count[rows[gid]], 1);
    if (gid < SCAN_BLOCKS) g_agg[gid] = 0;
}

// ---------------------------------------------------------------------------
// Kernel 2: single-pass exclusive scan of g_count -> g_start
// 49 co-resident blocks; decoupled lookback, full-predecessor stride.
// ---------------------------------------------------------------------------
__global__ __launch_bounds__(1024) void scan_fused_kernel() {
    __shared__ int wsum[32];
    __shared__ int blk_prev;
    const int t    = threadIdx.x;
    const int bid  = blockIdx.x;
    const int lane = t & 31;
    const int wid  = t >> 5;
    const int idx  = bid * 1024 + t;

    const int v = (idx < N_NODES) ? g_count[idx] : 0;

    int s = v;
    #pragma unroll
    for (int off = 1; off < 32; off <<= 1) {
        int n = __shfl_up_sync(0xffffffffu, s, off);
        if (lane >= off) s += n;
    }
    if (lane == 31) wsum[wid] = s;
    __syncthreads();

    if (wid == 0) {
        int ws = wsum[lane];
        #pragma unroll
        for (int off = 1; off < 32; off <<= 1) {
            int n = __shfl_up_sync(0xffffffffu, ws, off);
            if (lane >= off) ws += n;
        }
        wsum[lane] = ws;
        if (lane == 31) atomicExch(&g_agg[bid], ws | AGG_FLAG);

        int a = 0;
        for (int p = lane; p < bid; p += 32) {
            volatile int* agg = g_agg;
            int xv;
            do { xv = agg[p]; } while (!(xv & AGG_FLAG));
            a += xv & (AGG_FLAG - 1);
        }
        #pragma unroll
        for (int off = 16; off >= 1; off >>= 1)
            a += __shfl_xor_sync(0xffffffffu, a, off);
        if (lane == 0) blk_prev = a;
    }
    __syncthreads();

    const int wexcl = (wid > 0) ? wsum[wid - 1] : 0;
    if (idx < N_NODES) g_start[idx] = blk_prev + wexcl + (s - v);
    if (idx == 0) g_start[N_NODES] = N_EDGES;
}

// ---------------------------------------------------------------------------
// Kernel 3: GEMM (HMMA bf16 split-3) + FUSED CSR scatter
//   support = x @ W  with  AhBh + AhBl + AlBh
//   scatter: ~1600 edges/CTA hidden under the latency-bound GEMM phases.
// 512 threads; warp w owns rows [16*(w>>1), +16) x cols [64*(w&1), +64).
// ---------------------------------------------------------------------------
__global__ __launch_bounds__(GEMM_THREADS, 1)
void gemm_scatter_kernel(const float* __restrict__ x, const float* __restrict__ w,
                         const int*   __restrict__ rows,
                         const int*   __restrict__ cols,
                         const float* __restrict__ vals) {
    extern __shared__ char smem[];
    __nv_bfloat16* sAh = (__nv_bfloat16*)smem;                 // 128 x SPAD
    __nv_bfloat16* sAl = sAh + 128 * SPAD;
    __nv_bfloat16* sBh = sAl + 128 * SPAD;
    __nv_bfloat16* sBl = sBh + 128 * SPAD;

    const int t   = threadIdx.x;
    const int m0  = blockIdx.x * TILE_M;
    const int gid = blockIdx.x * GEMM_THREADS + t;

    // ---- Load + split x tile into smem (hi/lo bf16), padded stride ----
    #pragma unroll 4
    for (int i = 0; i < 8; i++) {
        int idx = t + GEMM_THREADS * i;        // 4096 float4 slots
        int row = idx >> 5;
        int c4  = (idx & 31) * 4;
        int m   = m0 + row;
        float4 xv = (m < N_NODES) ? ((const float4*)x)[((size_t)m * F + c4) >> 2]
                                  : make_float4(0.f, 0.f, 0.f, 0.f);
        __nv_bfloat16 h0 = __float2bfloat16(xv.x);
        __nv_bfloat16 h1 = __float2bfloat16(xv.y);
        __nv_bfloat16 h2 = __float2bfloat16(xv.z);
        __nv_bfloat16 h3 = __float2bfloat16(xv.w);
        __nv_bfloat16 l0 = __float2bfloat16(xv.x - __bfloat162float(h0));
        __nv_bfloat16 l1 = __float2bfloat16(xv.y - __bfloat162float(h1));
        __nv_bfloat16 l2 = __float2bfloat16(xv.z - __bfloat162float(h2));
        __nv_bfloat16 l3 = __float2bfloat16(xv.w - __bfloat162float(h3));
        uint2 hi, lo;
        hi.x = (uint32_t)__bfloat16_as_ushort(h0) | ((uint32_t)__bfloat16_as_ushort(h1) << 16);
        hi.y = (uint32_t)__bfloat16_as_ushort(h2) | ((uint32_t)__bfloat16_as_ushort(h3) << 16);
        lo.x = (uint32_t)__bfloat16_as_ushort(l0) | ((uint32_t)__bfloat16_as_ushort(l1) << 16);
        lo.y = (uint32_t)__bfloat16_as_ushort(l2) | ((uint32_t)__bfloat16_as_ushort(l3) << 16);
        int off = row * SPAD + c4;
        *(uint2*)&sAh[off] = hi;
        *(uint2*)&sAl[off] = lo;
    }

    // ---- W -> smem transposed + hi/lo split (B operand, [n][k]) ----
    #pragma unroll 4
    for (int i = 0; i < 32; i++) {
        int idx = t + GEMM_THREADS * i;        // 16384 elements, idx = k*128 + n
        int k = idx >> 7, n = idx & 127;
        float v = w[idx];                      // coalesced
        __nv_bfloat16 h = __float2bfloat16(v);
        __nv_bfloat16 l = __float2bfloat16(v - __bfloat162float(h));
        sBh[n * SPAD + k] = h;
        sBl[n * SPAD + k] = l;
    }

    // ---- FUSED scatter: edges -> CSR slots (independent of smem tiles) ----
    for (int e = gid; e < N_EDGES; e += GEMM_BLOCKS * GEMM_THREADS) {
        int r = rows[e];
        int p = g_start[r] + atomicSub(&g_count[r], 1) - 1;
        g_edge[p] = make_int2(cols[e], __float_as_int(vals[e]));
    }

    __syncthreads();

    const int wid  = t >> 5;
    const int lane = t & 31;
    const int R    = (wid >> 1) * 16;          // row base within tile
    const int C0   = (wid & 1) * 64;           // col base

    float acc[8][4];
    #pragma unroll
    for (int i = 0; i < 8; i++)
        #pragma unroll
        for (int j = 0; j < 4; j++) acc[i][j] = 0.f;

    const uint32_t base   = smem_u32(smem);
    const uint32_t aHbase = base;
    const uint32_t aLbase = base + TILE_BYTES;
    const uint32_t bHbase = base + 2 * TILE_BYTES;
    const uint32_t bLbase = base + 3 * TILE_BYTES;

    const int arow    = R + (lane & 7) + ((lane >> 3) & 1) * 8;
    const int acolh   = (lane >> 4) * 8;
    const int brow_in = (lane & 7) + ((lane >= 16) ? 8 : 0);
    const int bcolh   = ((lane >> 3) & 1) * 8;

    #pragma unroll 1
    for (int kc = 0; kc < 8; kc++) {
        const int k0 = kc * 16;
        const uint32_t aoff = (uint32_t)((arow * SPAD + k0 + acolh) * 2);
        uint32_t ah0, ah1, ah2, ah3, al0, al1, al2, al3;
        LDSM4(ah0, ah1, ah2, ah3, aHbase + aoff);
        LDSM4(al0, al1, al2, al3, aLbase + aoff);

        #pragma unroll
        for (int np = 0; np < 4; np++) {
            const int ncol = C0 + np * 16;
            const uint32_t boff = (uint32_t)(((ncol + brow_in) * SPAD + k0 + bcolh) * 2);
            uint32_t bh0, bh1, bh2, bh3, bl0, bl1, bl2, bl3;
            LDSM4(bh0, bh1, bh2, bh3, bHbase + boff);
            LDSM4(bl0, bl1, bl2, bl3, bLbase + boff);
            MMA16816(acc[2 * np],     ah0, ah1, ah2, ah3, bh0, bh1);
            MMA16816(acc[2 * np + 1], ah0, ah1, ah2, ah3, bh2, bh3);
            MMA16816(acc[2 * np],     ah0, ah1, ah2, ah3, bl0, bl1);
            MMA16816(acc[2 * np + 1], ah0, ah1, ah2, ah3, bl2, bl3);
            MMA16816(acc[2 * np],     al0, al1, al2, al3, bh0, bh1);
            MMA16816(acc[2 * np + 1], al0, al1, al2, al3, bh2, bh3);
        }
    }

    // ---- Epilogue: accum regs -> g_support (float2, full 32B sectors) ----
    const int g   = lane >> 2;
    const int tig = lane & 3;
    const int m1  = m0 + R + g;
    const int m2  = m1 + 8;
    #pragma unroll
    for (int nt = 0; nt < 8; nt++) {
        const int c = C0 + nt * 8 + tig * 2;
        if (m1 < N_NODES)
            *(float2*)&g_support[(size_t)m1 * F + c] = make_float2(acc[nt][0], acc[nt][1]);
        if (m2 < N_NODES)
            *(float2*)&g_support[(size_t)m2 * F + c] = make_float2(acc[nt][2], acc[nt][3]);
    }
}

// ---------------------------------------------------------------------------
// Kernel 4: CSR SpMM: warp per row, 4-edge ILP, atomic-free, bias fused
// ---------------------------------------------------------------------------
__global__ __launch_bounds__(256) void spmm_csr_kernel(const float* __restrict__ bias,
                                                       float*       __restrict__ out) {
    const int warp = (blockIdx.x * blockDim.x + threadIdx.x) >> 5;
    const int lane = threadIdx.x & 31;
    if (warp >= N_NODES) return;

    const int s = g_start[warp];
    const int e = g_start[warp + 1];

    float4 acc = ((const float4*)bias)[lane];

    int base = s;
    for (; base + 4 <= e; base += 4) {
        const int2 e0 = g_edge[base + 0];
        const int2 e1 = g_edge[base + 1];
        const int2 e2 = g_edge[base + 2];
        const int2 e3 = g_edge[base + 3];
        const float4 s0 = *(const float4*)&g_support[(size_t)e0.x * F + lane * 4];
        const float4 s1 = *(const float4*)&g_support[(size_t)e1.x * F + lane * 4];
        const float4 s2 = *(const float4*)&g_support[(size_t)e2.x * F + lane * 4];
        const float4 s3 = *(const float4*)&g_support[(size_t)e3.x * F + lane * 4];
        const float v0 = __int_as_float(e0.y);
        const float v1 = __int_as_float(e1.y);
        const float v2 = __int_as_float(e2.y);
        const float v3 = __int_as_float(e3.y);
        acc.x += v0 * s0.x; acc.y += v0 * s0.y; acc.z += v0 * s0.z; acc.w += v0 * s0.w;
        acc.x += v1 * s1.x; acc.y += v1 * s1.y; acc.z += v1 * s1.z; acc.w += v1 * s1.w;
        acc.x += v2 * s2.x; acc.y += v2 * s2.y; acc.z += v2 * s2.z; acc.w += v2 * s2.w;
        acc.x += v3 * s3.x; acc.y += v3 * s3.y; acc.z += v3 * s3.z; acc.w += v3 * s3.w;
    }
    for (; base < e; base++) {
        const int2  ed = g_edge[base];
        const float4 sv = *(const float4*)&g_support[(size_t)ed.x * F + lane * 4];
        const float  v  = __int_as_float(ed.y);
        acc.x += v * sv.x; acc.y += v * sv.y; acc.z += v * sv.z; acc.w += v * sv.w;
    }

    *(float4*)&out[(size_t)warp * F + lane * 4] = acc;
}

// ---------------------------------------------------------------------------
// Launch. Inputs: 0=x, 1=weight, 2=bias, 3=edge_vals, 4=edge_rows, 5=edge_cols
// ---------------------------------------------------------------------------
extern "C" void kernel_launch(void* const* d_in, const int* in_sizes, int n_in,
                              void* d_out, int out_size) {
    const float* x    = (const float*)d_in[0];
    const float* w    = (const float*)d_in[1];
    const float* bias = (const float*)d_in[2];
    const float* vals = (const float*)d_in[3];
    const int*   rows = (const int*)d_in[4];
    const int*   cols = (const int*)d_in[5];
    float*       out  = (float*)d_out;

    static bool attr_set = false;
    if (!attr_set) {
        cudaFuncSetAttribute(gemm_scatter_kernel,
                             cudaFuncAttributeMaxDynamicSharedMemorySize, GEMM_SMEM);
        attr_set = true;
    }

    // 1) histogram + flag reset
    hist_kernel<<<(N_EDGES + 255) / 256, 256>>>(rows);
    // 2) single-pass scan -> g_start
    scan_fused_kernel<<<SCAN_BLOCKS, 1024>>>();
    // 3) GEMM (support = x @ W) + fused CSR scatter (cursor back to 0)
    gemm_scatter_kernel<<<GEMM_BLOCKS, GEMM_THREADS, GEMM_SMEM>>>(x, w, rows, cols, vals);
    // 4) out = A_csr @ support + bias
    {
        const long long threads = (long long)N_NODES * 32;
        spmm_csr_kernel<<<(int)((threads + 255) / 256), 256>>>(bias, out);
    }
}

// round 11
// speedup vs baseline: 1.1560x; 1.1560x over previous
#include <cuda_runtime.h>
#include <cuda_bf16.h>
#include <cuda_fp16.h>
#include <cstdint>

#define N_NODES 50000
#define N_EDGES 625000
#define F 128
#define SCAN_BLOCKS 49          // 49 * 1024 = 50176 >= N_NODES
#define TILE_M 128
#define GEMM_BLOCKS ((N_NODES + TILE_M - 1) / TILE_M)   // 391
#define GEMM_THREADS 512
#define SPAD 136                // padded row stride (bf16 elems) -> conflict-free LDSM
#define TILE_BYTES (128 * SPAD * 2)
#define GEMM_SMEM (4 * TILE_BYTES)                      // Ah, Al, Bh, Bl = 139264 B
#define AGG_FLAG (1 << 30)

// ---------------------------------------------------------------------------
// Scratch (__device__ globals => allocation-free)
// Invariant: g_count[] == 0 at entry of every kernel_launch call.
// g_support is fp16: halves SpMM gather traffic; error budget ~3e-4 << 1e-3.
// ---------------------------------------------------------------------------
__device__ __half g_support[(size_t)N_NODES * F];  // x @ W, fp16 (12.8 MB)
__device__ int    g_count[N_NODES];                // histogram / cursor
__device__ int    g_start[N_NODES + 1];            // CSR row starts
__device__ int2   g_edge[N_EDGES];                 // packed {col, val} by row
__device__ int    g_agg[SCAN_BLOCKS];              // lookback aggregates

__device__ __forceinline__ uint32_t smem_u32(const void* p) {
    uint32_t a;
    asm("{ .reg .u64 t; cvta.to.shared.u64 t, %1; cvt.u32.u64 %0, t; }" : "=r"(a) : "l"(p));
    return a;
}

#define LDSM4(r0, r1, r2, r3, addr)                                              \
    asm volatile("ldmatrix.sync.aligned.m8n8.x4.shared.b16 {%0,%1,%2,%3}, [%4];" \
                 : "=r"(r0), "=r"(r1), "=r"(r2), "=r"(r3) : "r"(addr))

#define MMA16816(c, a0, a1, a2, a3, b0, b1)                                      \
    asm volatile("mma.sync.aligned.m16n8k16.row.col.f32.bf16.bf16.f32 "          \
                 "{%0,%1,%2,%3}, {%4,%5,%6,%7}, {%8,%9}, {%0,%1,%2,%3};"         \
                 : "+f"((c)[0]), "+f"((c)[1]), "+f"((c)[2]), "+f"((c)[3])        \
                 : "r"(a0), "r"(a1), "r"(a2), "r"(a3), "r"(b0), "r"(b1))

// ---------------------------------------------------------------------------
// Kernel 1: GEMM (HMMA bf16 split-3) + fused edge histogram + flag reset
//   support(fp16) = x @ W  with  AhBh + AhBl + AlBh
// 512 threads; warp w owns rows [16*(w>>1), +16) x cols [64*(w&1), +64).
// ---------------------------------------------------------------------------
__global__ __launch_bounds__(GEMM_THREADS, 1)
void gemm_hist_kernel(const float* __restrict__ x, const float* __restrict__ w,
                      const int* __restrict__ rows) {
    extern __shared__ char smem[];
    __nv_bfloat16* sAh = (__nv_bfloat16*)smem;                 // 128 x SPAD
    __nv_bfloat16* sAl = sAh + 128 * SPAD;
    __nv_bfloat16* sBh = sAl + 128 * SPAD;
    __nv_bfloat16* sBl = sBh + 128 * SPAD;

    const int t   = threadIdx.x;
    const int m0  = blockIdx.x * TILE_M;
    const int gid = blockIdx.x * GEMM_THREADS + t;

    // ---- Fused: edge-row histogram (fills idle issue slots) ----
    for (int e = gid; e < N_EDGES; e += GEMM_BLOCKS * GEMM_THREADS)
        atomicAdd(&g_count[rows[e]], 1);
    if (gid < SCAN_BLOCKS) g_agg[gid] = 0;

    // ---- Load + split x tile into smem (hi/lo bf16), padded stride ----
    #pragma unroll 4
    for (int i = 0; i < 8; i++) {
        int idx = t + GEMM_THREADS * i;        // 4096 float4 slots
        int row = idx >> 5;
        int c4  = (idx & 31) * 4;
        int m   = m0 + row;
        float4 xv = (m < N_NODES) ? ((const float4*)x)[((size_t)m * F + c4) >> 2]
                                  : make_float4(0.f, 0.f, 0.f, 0.f);
        __nv_bfloat16 h0 = __float2bfloat16(xv.x);
        __nv_bfloat16 h1 = __float2bfloat16(xv.y);
        __nv_bfloat16 h2 = __float2bfloat16(xv.z);
        __nv_bfloat16 h3 = __float2bfloat16(xv.w);
        __nv_bfloat16 l0 = __float2bfloat16(xv.x - __bfloat162float(h0));
        __nv_bfloat16 l1 = __float2bfloat16(xv.y - __bfloat162float(h1));
        __nv_bfloat16 l2 = __float2bfloat16(xv.z - __bfloat162float(h2));
        __nv_bfloat16 l3 = __float2bfloat16(xv.w - __bfloat162float(h3));
        uint2 hi, lo;
        hi.x = (uint32_t)__bfloat16_as_ushort(h0) | ((uint32_t)__bfloat16_as_ushort(h1) << 16);
        hi.y = (uint32_t)__bfloat16_as_ushort(h2) | ((uint32_t)__bfloat16_as_ushort(h3) << 16);
        lo.x = (uint32_t)__bfloat16_as_ushort(l0) | ((uint32_t)__bfloat16_as_ushort(l1) << 16);
        lo.y = (uint32_t)__bfloat16_as_ushort(l2) | ((uint32_t)__bfloat16_as_ushort(l3) << 16);
        int off = row * SPAD + c4;
        *(uint2*)&sAh[off] = hi;
        *(uint2*)&sAl[off] = lo;
    }

    // ---- W -> smem transposed + hi/lo split (B operand, [n][k]) ----
    #pragma unroll 4
    for (int i = 0; i < 32; i++) {
        int idx = t + GEMM_THREADS * i;        // 16384 elements, idx = k*128 + n
        int k = idx >> 7, n = idx & 127;
        float v = w[idx];                      // coalesced
        __nv_bfloat16 h = __float2bfloat16(v);
        __nv_bfloat16 l = __float2bfloat16(v - __bfloat162float(h));
        sBh[n * SPAD + k] = h;
        sBl[n * SPAD + k] = l;
    }
    __syncthreads();

    const int wid  = t >> 5;
    const int lane = t & 31;
    const int R    = (wid >> 1) * 16;          // row base within tile
    const int C0   = (wid & 1) * 64;           // col base

    float acc[8][4];
    #pragma unroll
    for (int i = 0; i < 8; i++)
        #pragma unroll
        for (int j = 0; j < 4; j++) acc[i][j] = 0.f;

    const uint32_t base   = smem_u32(smem);
    const uint32_t aHbase = base;
    const uint32_t aLbase = base + TILE_BYTES;
    const uint32_t bHbase = base + 2 * TILE_BYTES;
    const uint32_t bLbase = base + 3 * TILE_BYTES;

    const int arow    = R + (lane & 7) + ((lane >> 3) & 1) * 8;
    const int acolh   = (lane >> 4) * 8;
    const int brow_in = (lane & 7) + ((lane >= 16) ? 8 : 0);
    const int bcolh   = ((lane >> 3) & 1) * 8;

    #pragma unroll 1
    for (int kc = 0; kc < 8; kc++) {
        const int k0 = kc * 16;
        const uint32_t aoff = (uint32_t)((arow * SPAD + k0 + acolh) * 2);
        uint32_t ah0, ah1, ah2, ah3, al0, al1, al2, al3;
        LDSM4(ah0, ah1, ah2, ah3, aHbase + aoff);
        LDSM4(al0, al1, al2, al3, aLbase + aoff);

        #pragma unroll
        for (int np = 0; np < 4; np++) {
            const int ncol = C0 + np * 16;
            const uint32_t boff = (uint32_t)(((ncol + brow_in) * SPAD + k0 + bcolh) * 2);
            uint32_t bh0, bh1, bh2, bh3, bl0, bl1, bl2, bl3;
            LDSM4(bh0, bh1, bh2, bh3, bHbase + boff);
            LDSM4(bl0, bl1, bl2, bl3, bLbase + boff);
            MMA16816(acc[2 * np],     ah0, ah1, ah2, ah3, bh0, bh1);
            MMA16816(acc[2 * np + 1], ah0, ah1, ah2, ah3, bh2, bh3);
            MMA16816(acc[2 * np],     ah0, ah1, ah2, ah3, bl0, bl1);
            MMA16816(acc[2 * np + 1], ah0, ah1, ah2, ah3, bl2, bl3);
            MMA16816(acc[2 * np],     al0, al1, al2, al3, bh0, bh1);
            MMA16816(acc[2 * np + 1], al0, al1, al2, al3, bh2, bh3);
        }
    }

    // ---- Epilogue: accum regs -> g_support as fp16 (half2 per 2 cols) ----
    const int g   = lane >> 2;
    const int tig = lane & 3;
    const int m1  = m0 + R + g;
    const int m2  = m1 + 8;
    #pragma unroll
    for (int nt = 0; nt < 8; nt++) {
        const int c = C0 + nt * 8 + tig * 2;
        if (m1 < N_NODES)
            *(__half2*)&g_support[(size_t)m1 * F + c] = __floats2half2_rn(acc[nt][0], acc[nt][1]);
        if (m2 < N_NODES)
            *(__half2*)&g_support[(size_t)m2 * F + c] = __floats2half2_rn(acc[nt][2], acc[nt][3]);
    }
}

// ---------------------------------------------------------------------------
// Kernel 2: single-pass exclusive scan of g_count -> g_start
// ---------------------------------------------------------------------------
__global__ __launch_bounds__(1024) void scan_fused_kernel() {
    __shared__ int wsum[32];
    __shared__ int blk_prev;
    const int t    = threadIdx.x;
    const int bid  = blockIdx.x;
    const int lane = t & 31;
    const int wid  = t >> 5;
    const int idx  = bid * 1024 + t;

    const int v = (idx < N_NODES) ? g_count[idx] : 0;

    int s = v;
    #pragma unroll
    for (int off = 1; off < 32; off <<= 1) {
        int n = __shfl_up_sync(0xffffffffu, s, off);
        if (lane >= off) s += n;
    }
    if (lane == 31) wsum[wid] = s;
    __syncthreads();

    if (wid == 0) {
        int ws = wsum[lane];
        #pragma unroll
        for (int off = 1; off < 32; off <<= 1) {
            int n = __shfl_up_sync(0xffffffffu, ws, off);
            if (lane >= off) ws += n;
        }
        wsum[lane] = ws;
        if (lane == 31) atomicExch(&g_agg[bid], ws | AGG_FLAG);

        int a = 0;
        for (int p = lane; p < bid; p += 32) {
            volatile int* agg = g_agg;
            int xv;
            do { xv = agg[p]; } while (!(xv & AGG_FLAG));
            a += xv & (AGG_FLAG - 1);
        }
        #pragma unroll
        for (int off = 16; off >= 1; off >>= 1)
            a += __shfl_xor_sync(0xffffffffu, a, off);
        if (lane == 0) blk_prev = a;
    }
    __syncthreads();

    const int wexcl = (wid > 0) ? wsum[wid - 1] : 0;
    if (idx < N_NODES) g_start[idx] = blk_prev + wexcl + (s - v);
    if (idx == 0) g_start[N_NODES] = N_EDGES;
}

// ---------------------------------------------------------------------------
// Kernel 3: scatter edges into CSR order (atomicSub cursor -> back to 0)
// ---------------------------------------------------------------------------
__global__ void scatter_kernel(const int*   __restrict__ rows,
                               const int*   __restrict__ cols,
                               const float* __restrict__ vals) {
    int e = blockIdx.x * blockDim.x + threadIdx.x;
    if (e >= N_EDGES) return;
    int r = rows[e];
    int p = g_start[r] + atomicSub(&g_count[r], 1) - 1;
    g_edge[p] = make_int2(cols[e], __float_as_int(vals[e]));
}

// ---------------------------------------------------------------------------
// Kernel 4: CSR SpMM: warp per row, 4-edge ILP, atomic-free, bias fused.
// fp16 gathers (8B/lane = 256B/warp/edge), fp32 accumulation.
// ---------------------------------------------------------------------------
__device__ __forceinline__ void fma_half4(float4& acc, float v, uint2 u) {
    const __half2 h0 = *reinterpret_cast<__half2*>(&u.x);
    const __half2 h1 = *reinterpret_cast<__half2*>(&u.y);
    const float2 f0 = __half22float2(h0);
    const float2 f1 = __half22float2(h1);
    acc.x += v * f0.x; acc.y += v * f0.y;
    acc.z += v * f1.x; acc.w += v * f1.y;
}

__global__ __launch_bounds__(256) void spmm_csr_kernel(const float* __restrict__ bias,
                                                       float*       __restrict__ out) {
    const int warp = (blockIdx.x * blockDim.x + threadIdx.x) >> 5;
    const int lane = threadIdx.x & 31;
    if (warp >= N_NODES) return;

    const int s = g_start[warp];
    const int e = g_start[warp + 1];

    float4 acc = ((const float4*)bias)[lane];

    int base = s;
    for (; base + 4 <= e; base += 4) {
        const int2 e0 = g_edge[base + 0];
        const int2 e1 = g_edge[base + 1];
        const int2 e2 = g_edge[base + 2];
        const int2 e3 = g_edge[base + 3];
        const uint2 u0 = *(const uint2*)&g_support[(size_t)e0.x * F + lane * 4];
        const uint2 u1 = *(const uint2*)&g_support[(size_t)e1.x * F + lane * 4];
        const uint2 u2 = *(const uint2*)&g_support[(size_t)e2.x * F + lane * 4];
        const uint2 u3 = *(const uint2*)&g_support[(size_t)e3.x * F + lane * 4];
        fma_half4(acc, __int_as_float(e0.y), u0);
        fma_half4(acc, __int_as_float(e1.y), u1);
        fma_half4(acc, __int_as_float(e2.y), u2);
        fma_half4(acc, __int_as_float(e3.y), u3);
    }
    for (; base < e; base++) {
        const int2  ed = g_edge[base];
        const uint2 u  = *(const uint2*)&g_support[(size_t)ed.x * F + lane * 4];
        fma_half4(acc, __int_as_float(ed.y), u);
    }

    *(float4*)&out[(size_t)warp * F + lane * 4] = acc;
}

// ---------------------------------------------------------------------------
// Launch. Inputs: 0=x, 1=weight, 2=bias, 3=edge_vals, 4=edge_rows, 5=edge_cols
// ---------------------------------------------------------------------------
extern "C" void kernel_launch(void* const* d_in, const int* in_sizes, int n_in,
                              void* d_out, int out_size) {
    const float* x    = (const float*)d_in[0];
    const float* w    = (const float*)d_in[1];
    const float* bias = (const float*)d_in[2];
    const float* vals = (const float*)d_in[3];
    const int*   rows = (const int*)d_in[4];
    const int*   cols = (const int*)d_in[5];
    float*       out  = (float*)d_out;

    static bool attr_set = false;
    if (!attr_set) {
        cudaFuncSetAttribute(gemm_hist_kernel,
                             cudaFuncAttributeMaxDynamicSharedMemorySize, GEMM_SMEM);
        attr_set = true;
    }

    // 1) GEMM (support = x @ W, fp16 out) + fused histogram + flag reset
    gemm_hist_kernel<<<GEMM_BLOCKS, GEMM_THREADS, GEMM_SMEM>>>(x, w, rows);
    // 2) single-pass scan -> g_start
    scan_fused_kernel<<<SCAN_BLOCKS, 1024>>>();
    // 3) scatter into CSR order (cursor decrements back to 0)
    scatter_kernel<<<(N_EDGES + 255) / 256, 256>>>(rows, cols, vals);
    // 4) out = A_csr @ support + bias
    {
        const long long threads = (long long)N_NODES * 32;
        spmm_csr_kernel<<<(int)((threads + 255) / 256), 256>>>(bias, out);
    }
}